// round 5
// baseline (speedup 1.0000x reference)
#include <cuda_runtime.h>

#define BATCH 4
#define NQ    2048
#define NK    2048
#define DQ    1024
#define NH    8
#define HD    64
#define INNER 512
#define KKEEP 64
#define CAND_CAP 512

// Scratch (device globals; allocation-free contract)
__device__ float g_Q [BATCH * NQ * INNER];          // 16.8 MB
__device__ float g_KV[BATCH * NK * 2 * INNER];      // 33.5 MB  (K: cols 0..511, V: 512..1023)
__device__ float g_S [134217728];                   // 512 MB   sim [B*H][NQ][NK]
__device__ float g_O [BATCH * NQ * INNER];          // 16.8 MB

// ---- packed f32x2 helpers (FFMA2 is PTX-only on sm_103a) ---------------------
#define FMA2(acc, a, b) \
    asm("fma.rn.f32x2 %0, %1, %2, %0;" : "+l"(acc) : "l"(a), "l"(b))

__device__ __forceinline__ unsigned long long packdup(float f) {
    unsigned long long r;
    asm("mov.b64 %0, {%1, %1};" : "=l"(r) : "f"(f));
    return r;
}
__device__ __forceinline__ void unpack2(unsigned long long v, float& a, float& b) {
    asm("mov.b64 {%0, %1}, %2;" : "=f"(a), "=f"(b) : "l"(v));
}

// ---------------------------------------------------------------------------
// fp32 SGEMM (NN), double-buffered, FFMA2 inner product.
// C[M,N] = A[M,K] @ B[K,N] (+ bias). 128x128 tile, BK=8, 256 thr, 8x8 microtile.
// ---------------------------------------------------------------------------
__global__ void __launch_bounds__(256) sgemm_nn(
    const float* __restrict__ A, const float* __restrict__ Bm,
    const float* __restrict__ bias, float* __restrict__ C,
    int M, int N, int K)
{
    __shared__ float As[2][8][128];
    __shared__ float Bs[2][8][128];
    const int tid  = threadIdx.x;
    const int row0 = blockIdx.y * 128, col0 = blockIdx.x * 128;
    const int tx   = tid & 15, ty = tid >> 4;
    const int a_row = tid >> 1, a_k = (tid & 1) * 4;
    const int b_k   = tid >> 5, b_col = (tid & 31) * 4;
    const float* Ap = A  + (size_t)(row0 + a_row) * K + a_k;
    const float* Bp = Bm + (size_t)b_k * N + col0 + b_col;

    unsigned long long acc[8][4];
#pragma unroll
    for (int i = 0; i < 8; i++)
#pragma unroll
        for (int j = 0; j < 4; j++) acc[i][j] = 0ull;

    {
        float4 av = *(const float4*)Ap;
        float4 bv = *(const float4*)Bp;
        As[0][a_k + 0][a_row] = av.x;
        As[0][a_k + 1][a_row] = av.y;
        As[0][a_k + 2][a_row] = av.z;
        As[0][a_k + 3][a_row] = av.w;
        *(float4*)&Bs[0][b_k][b_col] = bv;
    }
    __syncthreads();

    int buf = 0;
    for (int k0 = 8; k0 <= K; k0 += 8) {
        const bool has = (k0 < K);
        float4 av, bv;
        if (has) {
            av = *(const float4*)(Ap + k0);
            bv = *(const float4*)(Bp + (size_t)k0 * N);
        }
#pragma unroll
        for (int kk = 0; kk < 8; kk++) {
            float4 a0 = *(const float4*)&As[buf][kk][ty * 4];
            float4 a1 = *(const float4*)&As[buf][kk][ty * 4 + 64];
            ulonglong2 b0 = *(const ulonglong2*)&Bs[buf][kk][tx * 4];
            ulonglong2 b1 = *(const ulonglong2*)&Bs[buf][kk][tx * 4 + 64];
            float af[8] = {a0.x, a0.y, a0.z, a0.w, a1.x, a1.y, a1.z, a1.w};
#pragma unroll
            for (int i = 0; i < 8; i++) {
                unsigned long long aa = packdup(af[i]);
                FMA2(acc[i][0], aa, b0.x);
                FMA2(acc[i][1], aa, b0.y);
                FMA2(acc[i][2], aa, b1.x);
                FMA2(acc[i][3], aa, b1.y);
            }
        }
        if (has) {
            const int nb = buf ^ 1;
            As[nb][a_k + 0][a_row] = av.x;
            As[nb][a_k + 1][a_row] = av.y;
            As[nb][a_k + 2][a_row] = av.z;
            As[nb][a_k + 3][a_row] = av.w;
            *(float4*)&Bs[nb][b_k][b_col] = bv;
            __syncthreads();
            buf = nb;
        }
    }

#pragma unroll
    for (int ih = 0; ih < 2; ih++)
#pragma unroll
        for (int ii = 0; ii < 4; ii++) {
            int i = ih * 4 + ii;
            int row = row0 + ty * 4 + ih * 64 + ii;
            float* Cp = C + (size_t)row * N + col0;
#pragma unroll
            for (int jh = 0; jh < 2; jh++) {
                int c = tx * 4 + jh * 64;
                float4 v;
                unpack2(acc[i][jh * 2 + 0], v.x, v.y);
                unpack2(acc[i][jh * 2 + 1], v.z, v.w);
                if (bias) {
                    v.x += bias[col0 + c + 0];
                    v.y += bias[col0 + c + 1];
                    v.z += bias[col0 + c + 2];
                    v.w += bias[col0 + c + 3];
                }
                *(float4*)(Cp + c) = v;
            }
        }
}

// ---------------------------------------------------------------------------
// sim[bh][i][j] = scale * sum_d Q[b,i,h*64+d] * K[b,j,h*64+d]   (NT, K=64)
// 128x128 tile, whole K=64 in smem (64KB dynamic), FFMA2 inner product.
// ---------------------------------------------------------------------------
__global__ void __launch_bounds__(256) sim_nt(
    const float* __restrict__ Q, const float* __restrict__ KV, float* __restrict__ S)
{
    extern __shared__ float smem[];
    float* Qs = smem;              // [64][128]  (d-major)
    float* Ks = smem + 64 * 128;   // [64][128]
    const int bh = blockIdx.z, b = bh >> 3, h = bh & 7;
    const int i0 = blockIdx.y * 128, j0 = blockIdx.x * 128;
    const int tid = threadIdx.x;

#pragma unroll
    for (int l = 0; l < 8; l++) {
        int idx = tid + l * 256;
        int row = idx >> 4, d0 = (idx & 15) * 4;
        float4 a = *(const float4*)(Q  + (size_t)(b * NQ + i0 + row) * INNER       + h * HD + d0);
        Qs[(d0 + 0) * 128 + row] = a.x; Qs[(d0 + 1) * 128 + row] = a.y;
        Qs[(d0 + 2) * 128 + row] = a.z; Qs[(d0 + 3) * 128 + row] = a.w;
        float4 v = *(const float4*)(KV + (size_t)(b * NK + j0 + row) * (2 * INNER) + h * HD + d0);
        Ks[(d0 + 0) * 128 + row] = v.x; Ks[(d0 + 1) * 128 + row] = v.y;
        Ks[(d0 + 2) * 128 + row] = v.z; Ks[(d0 + 3) * 128 + row] = v.w;
    }
    __syncthreads();

    const int tx = tid & 15, ty = tid >> 4;
    unsigned long long acc[8][4];
#pragma unroll
    for (int i = 0; i < 8; i++)
#pragma unroll
        for (int j = 0; j < 4; j++) acc[i][j] = 0ull;

#pragma unroll 4
    for (int d = 0; d < 64; d++) {
        float4 a0 = *(const float4*)(Qs + d * 128 + ty * 4);
        float4 a1 = *(const float4*)(Qs + d * 128 + ty * 4 + 64);
        ulonglong2 b0 = *(const ulonglong2*)(Ks + d * 128 + tx * 4);
        ulonglong2 b1 = *(const ulonglong2*)(Ks + d * 128 + tx * 4 + 64);
        float af[8] = {a0.x, a0.y, a0.z, a0.w, a1.x, a1.y, a1.z, a1.w};
#pragma unroll
        for (int i = 0; i < 8; i++) {
            unsigned long long aa = packdup(af[i]);
            FMA2(acc[i][0], aa, b0.x);
            FMA2(acc[i][1], aa, b0.y);
            FMA2(acc[i][2], aa, b1.x);
            FMA2(acc[i][3], aa, b1.y);
        }
    }

    const float scale = 0.125f;   // 64^-0.5
#pragma unroll
    for (int ih = 0; ih < 2; ih++)
#pragma unroll
        for (int ii = 0; ii < 4; ii++) {
            int i = ih * 4 + ii;
            int row = i0 + ty * 4 + ih * 64 + ii;
            float* Sp = S + ((size_t)bh * NQ + row) * NK + j0;
#pragma unroll
            for (int jh = 0; jh < 2; jh++) {
                int c = tx * 4 + jh * 64;
                float4 v;
                unpack2(acc[i][jh * 2 + 0], v.x, v.y);
                unpack2(acc[i][jh * 2 + 1], v.z, v.w);
                v.x *= scale; v.y *= scale; v.z *= scale; v.w *= scale;
                __stcs((float4*)(Sp + c), v);   // streaming: don't thrash L2
            }
        }
}

// ---------------------------------------------------------------------------
// Per query row: exact top-64 (2048-bin radix threshold, parallel scans),
// ties broken by lowest index (= jax.lax.top_k), softmax over survivors,
// sparse PV. One block (128 threads) per row.
// ---------------------------------------------------------------------------
__device__ __forceinline__ unsigned fkey(float f) {
    unsigned u = __float_as_uint(f);
    return (u & 0x80000000u) ? ~u : (u | 0x80000000u);
}

__global__ void __launch_bounds__(128, 12) topk_attn(
    const float* __restrict__ S, const float* __restrict__ KV, float* __restrict__ O)
{
    const int r  = blockIdx.x;
    const int bh = r >> 11, i = r & 2047;
    const int b  = bh >> 3, h = bh & 7;
    const float* srow = S + (size_t)r * NK;

    __shared__ unsigned hist[2048];
    __shared__ unsigned seg[128];      // suffix-scan workspace
    __shared__ float cval[CAND_CAP];
    __shared__ unsigned short cidx[CAND_CAP];
    __shared__ float selv[80];
    __shared__ int   seli[80];
    __shared__ int   s_nsel, s_ncand, s_thrbin, s_m, s_sseg, s_base;
    __shared__ float s_max, s_wsum;
    __shared__ float w[64];
    __shared__ float part[64];

    const int tid = threadIdx.x;
    for (int t = tid; t < 2048; t += 128) hist[t] = 0u;
    if (tid == 0) { s_nsel = 0; s_ncand = 0; }
    __syncthreads();

    float vals[16];
#pragma unroll
    for (int t = 0; t < 4; t++) {
        float4 v = __ldcs((const float4*)srow + tid + t * 128);
        vals[t * 4 + 0] = v.x; vals[t * 4 + 1] = v.y;
        vals[t * 4 + 2] = v.z; vals[t * 4 + 3] = v.w;
    }
#pragma unroll
    for (int t = 0; t < 16; t++)
        atomicAdd(&hist[fkey(vals[t]) >> 21], 1u);
    __syncthreads();

    // per-thread: sum of its 16-bin segment
    {
        unsigned s = 0;
#pragma unroll
        for (int q = 0; q < 16; q++) s += hist[tid * 16 + q];
        seg[tid] = s;
    }
    __syncthreads();

    // parallel suffix scan over 128 segments (Hillis-Steele, 7 steps)
#pragma unroll
    for (int off = 1; off < 128; off <<= 1) {
        unsigned v = seg[tid] + ((tid + off < 128) ? seg[tid + off] : 0u);
        __syncthreads();
        seg[tid] = v;
        __syncthreads();
    }
    {
        unsigned sfx  = seg[tid];
        unsigned sfx1 = (tid < 127) ? seg[tid + 1] : 0u;
        if (sfx >= KKEEP && sfx1 < KKEEP) { s_sseg = tid; s_base = (int)sfx1; }
    }
    __syncthreads();
    const int sseg = s_sseg, base = s_base;

    // within-segment crossing via warp 0 (16 lanes, shuffle suffix scan)
    if (tid < 32) {
        const int lane = tid;
        unsigned hv = (lane < 16) ? hist[sseg * 16 + lane] : 0u;
        unsigned sfx = hv;
#pragma unroll
        for (int off = 1; off < 16; off <<= 1) {
            unsigned t2 = __shfl_down_sync(0xffffffffu, sfx, off);
            if (lane + off < 16) sfx += t2;
        }
        if (lane < 16) {
            int above = base + (int)(sfx - hv);   // count strictly above this bin
            if (base + (int)sfx >= KKEEP && above < KKEEP) {
                s_thrbin = sseg * 16 + lane;
                s_m = KKEEP - above;
            }
        }
    }
    __syncthreads();
    const int thrbin = s_thrbin, m = s_m;

    // selection pass
#pragma unroll
    for (int t = 0; t < 16; t++) {
        int bin = (int)(fkey(vals[t]) >> 21);
        int j = (tid + (t >> 2) * 128) * 4 + (t & 3);
        if (bin > thrbin) {
            int p = atomicAdd(&s_nsel, 1);
            selv[p] = vals[t]; seli[p] = j;
        } else if (bin == thrbin) {
            int p = atomicAdd(&s_ncand, 1);
            if (p < CAND_CAP) { cval[p] = vals[t]; cidx[p] = (unsigned short)j; }
        }
    }
    __syncthreads();

    // tie-rank within threshold bin (ncand is small: ~6-30 typical)
    const int ncand = (s_ncand < CAND_CAP) ? s_ncand : CAND_CAP;
    for (int cpos = tid; cpos < ncand; cpos += 128) {
        float v = cval[cpos]; int jj = cidx[cpos];
        int rank = 0;
        for (int o = 0; o < ncand; o++) {
            float v2 = cval[o];
            rank += (v2 > v) || (v2 == v && (int)cidx[o] < jj);
        }
        if (rank < m) {
            int p = atomicAdd(&s_nsel, 1);
            selv[p] = v; seli[p] = jj;
        }
    }
    __syncthreads();   // s_nsel == 64 exactly

    if (tid < 32) {
        float mx = fmaxf(selv[tid], selv[tid + 32]);
#pragma unroll
        for (int off = 16; off; off >>= 1)
            mx = fmaxf(mx, __shfl_xor_sync(0xffffffffu, mx, off));
        if (tid == 0) s_max = mx;
    }
    __syncthreads();
    if (tid < 64) w[tid] = expf(selv[tid] - s_max);
    __syncthreads();
    if (tid < 32) {
        float s = w[tid] + w[tid + 32];
#pragma unroll
        for (int off = 16; off; off >>= 1)
            s += __shfl_xor_sync(0xffffffffu, s, off);
        if (tid == 0) s_wsum = s;
    }
    __syncthreads();

    const int g = tid >> 6, d = tid & 63;
    const float* Vbase = KV + (size_t)b * NK * (2 * INNER) + INNER + h * HD + d;
    float acc = 0.f;
#pragma unroll 4
    for (int jj = 0; jj < 32; jj++) {
        int j = g * 32 + jj;
        acc += w[j] * Vbase[(size_t)seli[j] * (2 * INNER)];
    }
    if (g == 1) part[d] = acc;
    __syncthreads();
    if (g == 0) {
        float o = (acc + part[d]) / s_wsum;
        O[((size_t)(b * NQ + i)) * INNER + h * HD + d] = o;
    }
}

// ---------------------------------------------------------------------------
extern "C" void kernel_launch(void* const* d_in, const int* in_sizes, int n_in,
                              void* d_out, int out_size)
{
    const float* x    = (const float*)d_in[0];
    const float* ctx  = (const float*)d_in[1];
    const float* Wq   = (const float*)d_in[2];
    const float* Wkv  = (const float*)d_in[3];
    const float* Wout = (const float*)d_in[4];
    const float* bout = (const float*)d_in[5];
    float* out = (float*)d_out;

    float *pQ, *pKV, *pS, *pO;
    cudaGetSymbolAddress((void**)&pQ,  g_Q);
    cudaGetSymbolAddress((void**)&pKV, g_KV);
    cudaGetSymbolAddress((void**)&pS,  g_S);
    cudaGetSymbolAddress((void**)&pO,  g_O);

    const int simSmem = 2 * 64 * 128 * sizeof(float);   // 64 KB
    cudaFuncSetAttribute(sim_nt, cudaFuncAttributeMaxDynamicSharedMemorySize, simSmem);

    dim3 blk(256);
    // Q = x @ Wq            [8192,1024] @ [1024,512]
    sgemm_nn<<<dim3(INNER / 128, BATCH * NQ / 128), blk>>>(x, Wq, nullptr, pQ,
                                                           BATCH * NQ, INNER, DQ);
    // KV = ctx @ Wkv        [8192,1024] @ [1024,1024]
    sgemm_nn<<<dim3(2 * INNER / 128, BATCH * NK / 128), blk>>>(ctx, Wkv, nullptr, pKV,
                                                               BATCH * NK, 2 * INNER, DQ);
    // sim = Q @ K^T * scale (batched per head)
    sim_nt<<<dim3(NK / 128, NQ / 128, BATCH * NH), blk, simSmem>>>(pQ, pKV, pS);
    // exact top-64 + softmax + sparse PV
    topk_attn<<<dim3(BATCH * NH * NQ), dim3(128)>>>(pS, pKV, pO);
    // out = O @ Wout + bout [8192,512] @ [512,1024]
    sgemm_nn<<<dim3(DQ / 128, BATCH * NQ / 128), blk>>>(pO, Wout, bout, out,
                                                        BATCH * NQ, DQ, INNER);
}

// round 6
// speedup vs baseline: 1.1316x; 1.1316x over previous
#include <cuda_runtime.h>

#define BATCH 4
#define NQ    2048
#define NK    2048
#define DQ    1024
#define NH    8
#define HD    64
#define INNER 512
#define KKEEP 64
#define CAND_CAP 512

// Scratch (device globals; allocation-free contract)
__device__ float g_Q [BATCH * NQ * INNER];          // 16.8 MB
__device__ float g_KV[BATCH * NK * 2 * INNER];      // 33.5 MB  (K: cols 0..511, V: 512..1023)
__device__ float g_S [134217728];                   // 512 MB   sim [B*H][NQ][NK]
__device__ float g_O [BATCH * NQ * INNER];          // 16.8 MB

// ---- tf32 split helpers + warp MMA --------------------------------------------
__device__ __forceinline__ void split_tf32(float v, unsigned& hi, unsigned& lo) {
    asm("cvt.rna.tf32.f32 %0, %1;" : "=r"(hi) : "f"(v));
    float l = v - __uint_as_float(hi);
    asm("cvt.rna.tf32.f32 %0, %1;" : "=r"(lo) : "f"(l));
}

#define MMA_TF32(c, a, b0, b1) \
    asm("mma.sync.aligned.m16n8k8.row.col.f32.tf32.tf32.f32 " \
        "{%0,%1,%2,%3}, {%4,%5,%6,%7}, {%8,%9}, {%0,%1,%2,%3};" \
        : "+f"((c)[0]), "+f"((c)[1]), "+f"((c)[2]), "+f"((c)[3]) \
        : "r"((a)[0]), "r"((a)[1]), "r"((a)[2]), "r"((a)[3]), "r"(b0), "r"(b1))

// ---------------------------------------------------------------------------
// fp32 SGEMM (NN), double-buffered (for Q and KV projections; precision-critical).
// 128x128 tile, BK=8, 256 threads, 8x8 microtile.
// ---------------------------------------------------------------------------
__global__ void __launch_bounds__(256) sgemm_nn(
    const float* __restrict__ A, const float* __restrict__ Bm,
    float* __restrict__ C, int M, int N, int K)
{
    __shared__ float As[2][8][128];
    __shared__ float Bs[2][8][128];
    const int tid  = threadIdx.x;
    const int row0 = blockIdx.y * 128, col0 = blockIdx.x * 128;
    const int tx   = tid & 15, ty = tid >> 4;
    const int a_row = tid >> 1, a_k = (tid & 1) * 4;
    const int b_k   = tid >> 5, b_col = (tid & 31) * 4;
    const float* Ap = A  + (size_t)(row0 + a_row) * K + a_k;
    const float* Bp = Bm + (size_t)b_k * N + col0 + b_col;

    float acc[8][8];
#pragma unroll
    for (int i = 0; i < 8; i++)
#pragma unroll
        for (int j = 0; j < 8; j++) acc[i][j] = 0.f;

    {
        float4 av = *(const float4*)Ap;
        float4 bv = *(const float4*)Bp;
        As[0][a_k + 0][a_row] = av.x;
        As[0][a_k + 1][a_row] = av.y;
        As[0][a_k + 2][a_row] = av.z;
        As[0][a_k + 3][a_row] = av.w;
        *(float4*)&Bs[0][b_k][b_col] = bv;
    }
    __syncthreads();

    int buf = 0;
    for (int k0 = 8; k0 <= K; k0 += 8) {
        const bool has = (k0 < K);
        float4 av, bv;
        if (has) {
            av = *(const float4*)(Ap + k0);
            bv = *(const float4*)(Bp + (size_t)k0 * N);
        }
#pragma unroll
        for (int kk = 0; kk < 8; kk++) {
            float af[8], bf[8];
            *(float4*)&af[0] = *(const float4*)&As[buf][kk][ty * 4];
            *(float4*)&af[4] = *(const float4*)&As[buf][kk][ty * 4 + 64];
            *(float4*)&bf[0] = *(const float4*)&Bs[buf][kk][tx * 4];
            *(float4*)&bf[4] = *(const float4*)&Bs[buf][kk][tx * 4 + 64];
#pragma unroll
            for (int i = 0; i < 8; i++)
#pragma unroll
                for (int j = 0; j < 8; j++)
                    acc[i][j] += af[i] * bf[j];
        }
        if (has) {
            const int nb = buf ^ 1;
            As[nb][a_k + 0][a_row] = av.x;
            As[nb][a_k + 1][a_row] = av.y;
            As[nb][a_k + 2][a_row] = av.z;
            As[nb][a_k + 3][a_row] = av.w;
            *(float4*)&Bs[nb][b_k][b_col] = bv;
            __syncthreads();
            buf = nb;
        }
    }

#pragma unroll
    for (int ih = 0; ih < 2; ih++)
#pragma unroll
        for (int ii = 0; ii < 4; ii++) {
            int row = row0 + ty * 4 + ih * 64 + ii;
            float* Cp = C + (size_t)row * N + col0;
#pragma unroll
            for (int jh = 0; jh < 2; jh++) {
                int c = tx * 4 + jh * 64;
                float4 v;
                v.x = acc[ih * 4 + ii][jh * 4 + 0];
                v.y = acc[ih * 4 + ii][jh * 4 + 1];
                v.z = acc[ih * 4 + ii][jh * 4 + 2];
                v.w = acc[ih * 4 + ii][jh * 4 + 3];
                *(float4*)(Cp + c) = v;
            }
        }
}

// ---------------------------------------------------------------------------
// sim via 3xTF32 tensor-core MMA (NT): S[bh][i][j] = 0.125 * Q_h[i,:] . K_h[j,:]
// Block = 128x128 S tile; Q/K tiles (raw fp32) in smem, split to tf32 at frag load.
// 8 warps, warp tile 32(M)x64(N), m16n8k8, K=64 in 8 steps.
// ---------------------------------------------------------------------------
__global__ void __launch_bounds__(256) sim_tf32(
    const float* __restrict__ Q, const float* __restrict__ KV, float* __restrict__ S)
{
    extern __shared__ float sm[];
    float* Qs = sm;              // [128][68]
    float* Ks = sm + 128 * 68;   // [128][68]
    const int bh = blockIdx.z, b = bh >> 3, h = bh & 7;
    const int i0 = blockIdx.y * 128, j0 = blockIdx.x * 128;
    const int tid = threadIdx.x;

#pragma unroll
    for (int l = 0; l < 8; l++) {
        int idx = tid + l * 256;
        int row = idx >> 4, k0 = (idx & 15) * 4;
        float4 q4 = *(const float4*)(Q  + (size_t)(b * NQ + i0 + row) * INNER       + h * HD + k0);
        *(float4*)(Qs + row * 68 + k0) = q4;
        float4 k4 = *(const float4*)(KV + (size_t)(b * NK + j0 + row) * (2 * INNER) + h * HD + k0);
        *(float4*)(Ks + row * 68 + k0) = k4;
    }
    __syncthreads();

    const int lane = tid & 31, wid = tid >> 5;
    const int wm = (wid & 3) * 32, wn = (wid >> 2) * 64;
    const int gr = lane >> 2, gc = lane & 3;

    float acc[2][8][4];
#pragma unroll
    for (int mi = 0; mi < 2; mi++)
#pragma unroll
        for (int ni = 0; ni < 8; ni++)
#pragma unroll
            for (int q = 0; q < 4; q++) acc[mi][ni][q] = 0.f;

#pragma unroll
    for (int k0 = 0; k0 < 64; k0 += 8) {
        unsigned ahi[2][4], alo[2][4];
#pragma unroll
        for (int mi = 0; mi < 2; mi++) {
            int m = wm + mi * 16 + gr;
            split_tf32(Qs[m * 68 + k0 + gc],           ahi[mi][0], alo[mi][0]);
            split_tf32(Qs[(m + 8) * 68 + k0 + gc],     ahi[mi][1], alo[mi][1]);
            split_tf32(Qs[m * 68 + k0 + 4 + gc],       ahi[mi][2], alo[mi][2]);
            split_tf32(Qs[(m + 8) * 68 + k0 + 4 + gc], ahi[mi][3], alo[mi][3]);
        }
#pragma unroll
        for (int ni = 0; ni < 8; ni++) {
            int n = wn + ni * 8 + gr;
            unsigned bh0, bl0, bh1, bl1;
            split_tf32(Ks[n * 68 + k0 + gc],     bh0, bl0);
            split_tf32(Ks[n * 68 + k0 + 4 + gc], bh1, bl1);
#pragma unroll
            for (int mi = 0; mi < 2; mi++) {
                MMA_TF32(acc[mi][ni], ahi[mi], bh0, bh1);
                MMA_TF32(acc[mi][ni], ahi[mi], bl0, bl1);
                MMA_TF32(acc[mi][ni], alo[mi], bh0, bh1);
            }
        }
    }

    const float scale = 0.125f;
#pragma unroll
    for (int mi = 0; mi < 2; mi++)
#pragma unroll
        for (int ni = 0; ni < 8; ni++) {
            int row = i0 + wm + mi * 16 + gr;
            int col = j0 + wn + ni * 8 + gc * 2;
            float2 v0 = { acc[mi][ni][0] * scale, acc[mi][ni][1] * scale };
            __stcs((float2*)(S + ((size_t)bh * NQ + row) * NK + col), v0);
            float2 v1 = { acc[mi][ni][2] * scale, acc[mi][ni][3] * scale };
            __stcs((float2*)(S + ((size_t)bh * NQ + row + 8) * NK + col), v1);
        }
}

// ---------------------------------------------------------------------------
// out-projection via 3xTF32 MMA (NN): C[8192,1024] = O[8192,512] @ Wout + bias
// Block 128x128, BK=8 double-buffered; B transposed into smem at load.
// ---------------------------------------------------------------------------
__global__ void __launch_bounds__(256) out_tf32(
    const float* __restrict__ A, const float* __restrict__ Bm,
    const float* __restrict__ bias, float* __restrict__ C)
{
    __shared__ float As[2][128 * 12];
    __shared__ float Bs[2][128 * 12];
    const int tid  = threadIdx.x;
    const int row0 = blockIdx.y * 128, col0 = blockIdx.x * 128;
    const int a_row = tid >> 1, a_k = (tid & 1) * 4;
    const int b_k   = tid >> 5, b_n = (tid & 31) * 4;
    const float* Ap = A  + (size_t)(row0 + a_row) * INNER + a_k;
    const float* Bp = Bm + (size_t)b_k * DQ + col0 + b_n;

    {
        float4 a4 = *(const float4*)Ap;
        *(float4*)(As[0] + a_row * 12 + a_k) = a4;
        float4 b4 = *(const float4*)Bp;
        Bs[0][(b_n + 0) * 12 + b_k] = b4.x;
        Bs[0][(b_n + 1) * 12 + b_k] = b4.y;
        Bs[0][(b_n + 2) * 12 + b_k] = b4.z;
        Bs[0][(b_n + 3) * 12 + b_k] = b4.w;
    }
    __syncthreads();

    const int lane = tid & 31, wid = tid >> 5;
    const int wm = (wid & 3) * 32, wn = (wid >> 2) * 64;
    const int gr = lane >> 2, gc = lane & 3;

    float acc[2][8][4];
#pragma unroll
    for (int mi = 0; mi < 2; mi++)
#pragma unroll
        for (int ni = 0; ni < 8; ni++)
#pragma unroll
            for (int q = 0; q < 4; q++) acc[mi][ni][q] = 0.f;

    int buf = 0;
    for (int k0 = 8; k0 <= INNER; k0 += 8) {
        const bool has = (k0 < INNER);
        float4 a4, b4;
        if (has) {
            a4 = *(const float4*)(Ap + k0);
            b4 = *(const float4*)(Bp + (size_t)k0 * DQ);
        }
        unsigned ahi[2][4], alo[2][4];
#pragma unroll
        for (int mi = 0; mi < 2; mi++) {
            int m = wm + mi * 16 + gr;
            split_tf32(As[buf][m * 12 + gc],           ahi[mi][0], alo[mi][0]);
            split_tf32(As[buf][(m + 8) * 12 + gc],     ahi[mi][1], alo[mi][1]);
            split_tf32(As[buf][m * 12 + 4 + gc],       ahi[mi][2], alo[mi][2]);
            split_tf32(As[buf][(m + 8) * 12 + 4 + gc], ahi[mi][3], alo[mi][3]);
        }
#pragma unroll
        for (int ni = 0; ni < 8; ni++) {
            int n = wn + ni * 8 + gr;
            unsigned bh0, bl0, bh1, bl1;
            split_tf32(Bs[buf][n * 12 + gc],     bh0, bl0);
            split_tf32(Bs[buf][n * 12 + 4 + gc], bh1, bl1);
#pragma unroll
            for (int mi = 0; mi < 2; mi++) {
                MMA_TF32(acc[mi][ni], ahi[mi], bh0, bh1);
                MMA_TF32(acc[mi][ni], ahi[mi], bl0, bl1);
                MMA_TF32(acc[mi][ni], alo[mi], bh0, bh1);
            }
        }
        if (has) {
            const int nb = buf ^ 1;
            *(float4*)(As[nb] + a_row * 12 + a_k) = a4;
            Bs[nb][(b_n + 0) * 12 + b_k] = b4.x;
            Bs[nb][(b_n + 1) * 12 + b_k] = b4.y;
            Bs[nb][(b_n + 2) * 12 + b_k] = b4.z;
            Bs[nb][(b_n + 3) * 12 + b_k] = b4.w;
            __syncthreads();
            buf = nb;
        }
    }

#pragma unroll
    for (int mi = 0; mi < 2; mi++)
#pragma unroll
        for (int ni = 0; ni < 8; ni++) {
            int row = row0 + wm + mi * 16 + gr;
            int col = col0 + wn + ni * 8 + gc * 2;
            float bx = bias[col], by = bias[col + 1];
            float2 v0 = { acc[mi][ni][0] + bx, acc[mi][ni][1] + by };
            *(float2*)(C + (size_t)row * DQ + col) = v0;
            float2 v1 = { acc[mi][ni][2] + bx, acc[mi][ni][3] + by };
            *(float2*)(C + (size_t)(row + 8) * DQ + col) = v1;
        }
}

// ---------------------------------------------------------------------------
// Per query row: exact top-64 (2048-bin radix threshold, parallel scans),
// ties broken by lowest index (= jax.lax.top_k), softmax over survivors,
// sparse PV. One block (128 threads) per row.
// ---------------------------------------------------------------------------
__device__ __forceinline__ unsigned fkey(float f) {
    unsigned u = __float_as_uint(f);
    return (u & 0x80000000u) ? ~u : (u | 0x80000000u);
}

__global__ void __launch_bounds__(128, 12) topk_attn(
    const float* __restrict__ S, const float* __restrict__ KV, float* __restrict__ O)
{
    const int r  = blockIdx.x;
    const int bh = r >> 11, i = r & 2047;
    const int b  = bh >> 3, h = bh & 7;
    const float* srow = S + (size_t)r * NK;

    __shared__ unsigned hist[2048];
    __shared__ unsigned seg[128];
    __shared__ float cval[CAND_CAP];
    __shared__ unsigned short cidx[CAND_CAP];
    __shared__ float selv[80];
    __shared__ int   seli[80];
    __shared__ int   s_nsel, s_ncand, s_thrbin, s_m, s_sseg, s_base;
    __shared__ float s_max, s_wsum;
    __shared__ float w[64];
    __shared__ float part[64];

    const int tid = threadIdx.x;
    for (int t = tid; t < 2048; t += 128) hist[t] = 0u;
    if (tid == 0) { s_nsel = 0; s_ncand = 0; }
    __syncthreads();

    float vals[16];
#pragma unroll
    for (int t = 0; t < 4; t++) {
        float4 v = __ldcs((const float4*)srow + tid + t * 128);
        vals[t * 4 + 0] = v.x; vals[t * 4 + 1] = v.y;
        vals[t * 4 + 2] = v.z; vals[t * 4 + 3] = v.w;
    }
#pragma unroll
    for (int t = 0; t < 16; t++)
        atomicAdd(&hist[fkey(vals[t]) >> 21], 1u);
    __syncthreads();

    {
        unsigned s = 0;
#pragma unroll
        for (int q = 0; q < 16; q++) s += hist[tid * 16 + q];
        seg[tid] = s;
    }
    __syncthreads();

#pragma unroll
    for (int off = 1; off < 128; off <<= 1) {
        unsigned v = seg[tid] + ((tid + off < 128) ? seg[tid + off] : 0u);
        __syncthreads();
        seg[tid] = v;
        __syncthreads();
    }
    {
        unsigned sfx  = seg[tid];
        unsigned sfx1 = (tid < 127) ? seg[tid + 1] : 0u;
        if (sfx >= KKEEP && sfx1 < KKEEP) { s_sseg = tid; s_base = (int)sfx1; }
    }
    __syncthreads();
    const int sseg = s_sseg, base = s_base;

    if (tid < 32) {
        const int lane = tid;
        unsigned hv = (lane < 16) ? hist[sseg * 16 + lane] : 0u;
        unsigned sfx = hv;
#pragma unroll
        for (int off = 1; off < 16; off <<= 1) {
            unsigned t2 = __shfl_down_sync(0xffffffffu, sfx, off);
            if (lane + off < 16) sfx += t2;
        }
        if (lane < 16) {
            int above = base + (int)(sfx - hv);
            if (base + (int)sfx >= KKEEP && above < KKEEP) {
                s_thrbin = sseg * 16 + lane;
                s_m = KKEEP - above;
            }
        }
    }
    __syncthreads();
    const int thrbin = s_thrbin, m = s_m;

#pragma unroll
    for (int t = 0; t < 16; t++) {
        int bin = (int)(fkey(vals[t]) >> 21);
        int j = (tid + (t >> 2) * 128) * 4 + (t & 3);
        if (bin > thrbin) {
            int p = atomicAdd(&s_nsel, 1);
            selv[p] = vals[t]; seli[p] = j;
        } else if (bin == thrbin) {
            int p = atomicAdd(&s_ncand, 1);
            if (p < CAND_CAP) { cval[p] = vals[t]; cidx[p] = (unsigned short)j; }
        }
    }
    __syncthreads();

    const int ncand = (s_ncand < CAND_CAP) ? s_ncand : CAND_CAP;
    for (int cpos = tid; cpos < ncand; cpos += 128) {
        float v = cval[cpos]; int jj = cidx[cpos];
        int rank = 0;
        for (int o = 0; o < ncand; o++) {
            float v2 = cval[o];
            rank += (v2 > v) || (v2 == v && (int)cidx[o] < jj);
        }
        if (rank < m) {
            int p = atomicAdd(&s_nsel, 1);
            selv[p] = v; seli[p] = jj;
        }
    }
    __syncthreads();   // s_nsel == 64 exactly

    if (tid < 32) {
        float mx = fmaxf(selv[tid], selv[tid + 32]);
#pragma unroll
        for (int off = 16; off; off >>= 1)
            mx = fmaxf(mx, __shfl_xor_sync(0xffffffffu, mx, off));
        if (tid == 0) s_max = mx;
    }
    __syncthreads();
    if (tid < 64) w[tid] = expf(selv[tid] - s_max);
    __syncthreads();
    if (tid < 32) {
        float s = w[tid] + w[tid + 32];
#pragma unroll
        for (int off = 16; off; off >>= 1)
            s += __shfl_xor_sync(0xffffffffu, s, off);
        if (tid == 0) s_wsum = s;
    }
    __syncthreads();

    const int g = tid >> 6, d = tid & 63;
    const float* Vbase = KV + (size_t)b * NK * (2 * INNER) + INNER + h * HD + d;
    float acc = 0.f;
#pragma unroll 4
    for (int jj = 0; jj < 32; jj++) {
        int j = g * 32 + jj;
        acc += w[j] * Vbase[(size_t)seli[j] * (2 * INNER)];
    }
    if (g == 1) part[d] = acc;
    __syncthreads();
    if (g == 0) {
        float o = (acc + part[d]) / s_wsum;
        O[((size_t)(b * NQ + i)) * INNER + h * HD + d] = o;
    }
}

// ---------------------------------------------------------------------------
extern "C" void kernel_launch(void* const* d_in, const int* in_sizes, int n_in,
                              void* d_out, int out_size)
{
    const float* x    = (const float*)d_in[0];
    const float* ctx  = (const float*)d_in[1];
    const float* Wq   = (const float*)d_in[2];
    const float* Wkv  = (const float*)d_in[3];
    const float* Wout = (const float*)d_in[4];
    const float* bout = (const float*)d_in[5];
    float* out = (float*)d_out;

    float *pQ, *pKV, *pS, *pO;
    cudaGetSymbolAddress((void**)&pQ,  g_Q);
    cudaGetSymbolAddress((void**)&pKV, g_KV);
    cudaGetSymbolAddress((void**)&pS,  g_S);
    cudaGetSymbolAddress((void**)&pO,  g_O);

    const int simSmem = 2 * 128 * 68 * sizeof(float);   // 69632 B
    cudaFuncSetAttribute(sim_tf32, cudaFuncAttributeMaxDynamicSharedMemorySize, simSmem);

    dim3 blk(256);
    // Q = x @ Wq            [8192,1024] @ [1024,512]     (fp32, precision-critical)
    sgemm_nn<<<dim3(INNER / 128, BATCH * NQ / 128), blk>>>(x, Wq, pQ,
                                                           BATCH * NQ, INNER, DQ);
    // KV = ctx @ Wkv        [8192,1024] @ [1024,1024]    (fp32, precision-critical)
    sgemm_nn<<<dim3(2 * INNER / 128, BATCH * NK / 128), blk>>>(ctx, Wkv, pKV,
                                                               BATCH * NK, 2 * INNER, DQ);
    // sim = Q @ K^T * scale (3xTF32 tensor cores)
    sim_tf32<<<dim3(NK / 128, NQ / 128, BATCH * NH), blk, simSmem>>>(pQ, pKV, pS);
    // exact top-64 + softmax + sparse PV
    topk_attn<<<dim3(BATCH * NH * NQ), dim3(128)>>>(pS, pKV, pO);
    // out = O @ Wout + bout [8192,512] @ [512,1024]      (3xTF32 tensor cores)
    out_tf32<<<dim3(DQ / 128, BATCH * NQ / 128), blk>>>(pO, Wout, bout, out);
}